// round 1
// baseline (speedup 1.0000x reference)
#include <cuda_runtime.h>

#define TPB 256
#define MAXB 4096

// Flag set by the detector kernel: 1 if `batch` is int64 (odd int32 words are
// the zero high-halves), 0 if int32. Deterministic for fixed inputs.
__device__ int g_batch_is64;

__global__ void detect_idx_kernel(const int* __restrict__ b32) {
    if (threadIdx.x == 0) {
        int z = 0;
#pragma unroll
        for (int i = 1; i < 64; i += 2) z |= b32[i];
        g_batch_is64 = (z == 0) ? 1 : 0;
    }
}

__global__ void __launch_bounds__(TPB) edge_mlp_kernel(
    const float* __restrict__ src, const float* __restrict__ dst,
    const float* __restrict__ ea,  const float* __restrict__ u,
    const int* __restrict__ batch32,
    const float* __restrict__ W1, const float* __restrict__ b1,
    const float* __restrict__ W2, const float* __restrict__ b2,
    float* __restrict__ out, int E, int B)
{
    __shared__ __align__(16) float sW1T[10][4];   // sW1T[j][k] = W1[k][j]
    __shared__ float sb1[10];
    __shared__ __align__(16) float sW2[10][20];   // padded row stride 20 for float4
    __shared__ __align__(16) float sb2[20];
    __shared__ float su[MAXB];
    __shared__ __align__(16) float sout[TPB * 19];

    const int tid = threadIdx.x;

    // ---- load tiny weights + u table into shared ----
    if (tid < 40) {                       // W1 is [4][10] row-major
        int k = tid / 10, j = tid % 10;
        sW1T[j][k] = W1[tid];
    }
    if (tid < 10) sb1[tid] = b1[tid];
    if (tid < 200) {                      // W2 is [10][19] row-major, pad col 19 with 0
        int j = tid / 20, c = tid % 20;
        sW2[j][c] = (c < 19) ? W2[j * 19 + c] : 0.0f;
    }
    if (tid < 20) sb2[tid] = (tid < 19) ? b2[tid] : 0.0f;
    int nB = (B < MAXB) ? B : MAXB;
    for (int i = tid; i < nB; i += TPB) su[i] = u[i];

    const int is64 = g_batch_is64;        // uniform
    __syncthreads();

    const int blockStart = blockIdx.x * TPB;
    const int e = blockStart + tid;

    if (e < E) {
        // streaming input loads (no L2 reuse)
        float s = __ldcs(src + e);
        float d = __ldcs(dst + e);
        float a = __ldcs(ea + e);
        int  bi = __ldcs(batch32 + ((size_t)e << is64));  // stride 2 words if int64
        float ub = su[bi];

        float o[19];
#pragma unroll
        for (int c = 0; c < 19; c++) o[c] = sb2[c];

#pragma unroll
        for (int j = 0; j < 10; j++) {
            float4 w1 = *reinterpret_cast<const float4*>(&sW1T[j][0]);
            float h = fmaf(s, w1.x, fmaf(d, w1.y, fmaf(a, w1.z, fmaf(ub, w1.w, sb1[j]))));
            h = fmaxf(h, 0.0f);

            const float4* wr = reinterpret_cast<const float4*>(&sW2[j][0]);
            float wv[20];
            *reinterpret_cast<float4*>(&wv[0])  = wr[0];
            *reinterpret_cast<float4*>(&wv[4])  = wr[1];
            *reinterpret_cast<float4*>(&wv[8])  = wr[2];
            *reinterpret_cast<float4*>(&wv[12]) = wr[3];
            *reinterpret_cast<float4*>(&wv[16]) = wr[4];
#pragma unroll
            for (int c = 0; c < 19; c++) o[c] = fmaf(h, wv[c], o[c]);
        }

        // stage: stride 19 is coprime with 32 -> conflict-free STS
#pragma unroll
        for (int c = 0; c < 19; c++) sout[tid * 19 + c] = o[c];
    }
    __syncthreads();

    // ---- coalesced streaming copy-out (block region is float4 aligned) ----
    int nvalid = E - blockStart;
    if (nvalid > TPB) nvalid = TPB;
    const int nf  = nvalid * 19;
    const int nf4 = nf >> 2;
    float4* gout = reinterpret_cast<float4*>(out + (size_t)blockStart * 19);
    const float4* sf = reinterpret_cast<const float4*>(sout);
    for (int i = tid; i < nf4; i += TPB) {
        __stcs(gout + i, sf[i]);
    }
    if (tid < (nf & 3)) {
        out[(size_t)blockStart * 19 + nf4 * 4 + tid] = sout[nf4 * 4 + tid];
    }
}

extern "C" void kernel_launch(void* const* d_in, const int* in_sizes, int n_in,
                              void* d_out, int out_size)
{
    const float* src   = (const float*)d_in[0];
    const float* dst   = (const float*)d_in[1];
    const float* ea    = (const float*)d_in[2];
    const float* u     = (const float*)d_in[3];
    const int*   batch = (const int*)d_in[4];   // int32 view; detector resolves width
    const float* W1    = (const float*)d_in[5];
    const float* b1    = (const float*)d_in[6];
    const float* W2    = (const float*)d_in[7];
    const float* b2    = (const float*)d_in[8];

    const int E = in_sizes[0];
    const int B = in_sizes[3];

    detect_idx_kernel<<<1, 32>>>(batch);

    const int grid = (E + TPB - 1) / TPB;
    edge_mlp_kernel<<<grid, TPB>>>(src, dst, ea, u, batch,
                                   W1, b1, W2, b2, (float*)d_out, E, B);
}

// round 5
// speedup vs baseline: 1.1950x; 1.1950x over previous
#include <cuda_runtime.h>

#define TPB   256
#define WARPS (TPB / 32)
#define EPW   64                 // edges per warp (ILP=2 per thread)
#define EPB   (WARPS * EPW)      // 512 edges per block

// 1 if `batch` is int64 (odd int32 words are zero high-halves), else 0.
__device__ int g_batch_is64;

__global__ void detect_idx_kernel(const int* __restrict__ b32) {
    if (threadIdx.x == 0) {
        int z = 0;
#pragma unroll
        for (int i = 1; i < 64; i += 2) z |= b32[i];
        g_batch_is64 = (z == 0) ? 1 : 0;
    }
}

__global__ void __launch_bounds__(TPB, 2) edge_mlp_kernel(
    const float* __restrict__ src, const float* __restrict__ dst,
    const float* __restrict__ ea,  const float* __restrict__ u,
    const int* __restrict__ batch32,
    const float* __restrict__ W1, const float* __restrict__ b1,
    const float* __restrict__ W2, const float* __restrict__ b2,
    float* __restrict__ out, int E, int B)
{
    __shared__ __align__(16) float wbuf[WARPS][EPW * 19];  // 4864 B per warp
    __shared__ __align__(16) float sW1T[10][4];            // sW1T[j][k] = W1[k][j]
    __shared__ float sb1[10];
    __shared__ __align__(16) float sW2[10][20];            // row-padded to 20
    __shared__ float sb2[20];

    const int tid  = threadIdx.x;
    const int lane = tid & 31;
    const int w    = tid >> 5;

    if (tid < 40)  sW1T[tid % 10][tid / 10] = W1[tid];
    if (tid < 10)  sb1[tid] = b1[tid];
    if (tid < 200) { int j = tid / 20, c = tid % 20;
                     sW2[j][c] = (c < 19) ? W2[j * 19 + c] : 0.0f; }
    if (tid < 20)  sb2[tid] = (tid < 19) ? b2[tid] : 0.0f;
    const int is64 = g_batch_is64;                         // uniform
    __syncthreads();

    const int we0 = blockIdx.x * EPB + w * EPW;            // warp's first edge

    // ---- inputs (coalesced, streaming) ----
    float xs[2], xd[2], xa[2], xu[2];
    float o[2][19];
#pragma unroll
    for (int p = 0; p < 2; p++) {
        int e  = we0 + p * 32 + lane;
        int ec = (e < E) ? e : 0;
        xs[p] = __ldcs(src + ec);
        xd[p] = __ldcs(dst + ec);
        xa[p] = __ldcs(ea + ec);
        int bi = __ldcs(batch32 + ((size_t)ec << is64));
        xu[p] = __ldg(u + bi);                             // 16 KB table, L1-resident
#pragma unroll
        for (int c = 0; c < 19; c++) o[p][c] = sb2[c];
    }

    // ---- fused MLP: j-loop, weight rows loaded once per thread for 2 edges ----
#pragma unroll
    for (int j = 0; j < 10; j++) {
        float4 w1 = *reinterpret_cast<const float4*>(&sW1T[j][0]);
        float  bj = sb1[j];
        const float4* wr = reinterpret_cast<const float4*>(&sW2[j][0]);
        float4 wa = wr[0], wb = wr[1], wc4 = wr[2], wd = wr[3], we4 = wr[4];
#pragma unroll
        for (int p = 0; p < 2; p++) {
            float h = fmaf(xs[p], w1.x, fmaf(xd[p], w1.y,
                      fmaf(xa[p], w1.z, fmaf(xu[p], w1.w, bj))));
            h = fmaxf(h, 0.0f);
            o[p][0]  = fmaf(h, wa.x,  o[p][0]);
            o[p][1]  = fmaf(h, wa.y,  o[p][1]);
            o[p][2]  = fmaf(h, wa.z,  o[p][2]);
            o[p][3]  = fmaf(h, wa.w,  o[p][3]);
            o[p][4]  = fmaf(h, wb.x,  o[p][4]);
            o[p][5]  = fmaf(h, wb.y,  o[p][5]);
            o[p][6]  = fmaf(h, wb.z,  o[p][6]);
            o[p][7]  = fmaf(h, wb.w,  o[p][7]);
            o[p][8]  = fmaf(h, wc4.x, o[p][8]);
            o[p][9]  = fmaf(h, wc4.y, o[p][9]);
            o[p][10] = fmaf(h, wc4.z, o[p][10]);
            o[p][11] = fmaf(h, wc4.w, o[p][11]);
            o[p][12] = fmaf(h, wd.x,  o[p][12]);
            o[p][13] = fmaf(h, wd.y,  o[p][13]);
            o[p][14] = fmaf(h, wd.z,  o[p][14]);
            o[p][15] = fmaf(h, wd.w,  o[p][15]);
            o[p][16] = fmaf(h, we4.x, o[p][16]);
            o[p][17] = fmaf(h, we4.y, o[p][17]);
            o[p][18] = fmaf(h, we4.z, o[p][18]);
        }
    }

    // ---- stage to warp-private buffer (stride 19: conflict-free) ----
#pragma unroll
    for (int p = 0; p < 2; p++) {
        int el = p * 32 + lane;
        if (we0 + el < E) {
#pragma unroll
            for (int c = 0; c < 19; c++) wbuf[w][el * 19 + c] = o[p][c];
        }
    }
    __syncwarp();

    // ---- coalesced streaming copy-out (warp base is 16B-aligned: 64*76B) ----
    int nv = E - we0;
    if (nv > EPW) nv = EPW;
    if (nv < 0)   nv = 0;
    const int nf  = nv * 19;
    const int nf4 = nf >> 2;
    float4* gout = reinterpret_cast<float4*>(out + (size_t)we0 * 19);
    const float4* sf = reinterpret_cast<const float4*>(&wbuf[w][0]);
    for (int i = lane; i < nf4; i += 32) __stcs(gout + i, sf[i]);
    if (lane < (nf & 3))
        out[(size_t)we0 * 19 + nf4 * 4 + lane] = wbuf[w][nf4 * 4 + lane];
}

extern "C" void kernel_launch(void* const* d_in, const int* in_sizes, int n_in,
                              void* d_out, int out_size)
{
    const float* src   = (const float*)d_in[0];
    const float* dst   = (const float*)d_in[1];
    const float* ea    = (const float*)d_in[2];
    const float* u     = (const float*)d_in[3];
    const int*   batch = (const int*)d_in[4];
    const float* W1    = (const float*)d_in[5];
    const float* b1    = (const float*)d_in[6];
    const float* W2    = (const float*)d_in[7];
    const float* b2    = (const float*)d_in[8];

    const int E = in_sizes[0];
    const int B = in_sizes[3];

    detect_idx_kernel<<<1, 32>>>(batch);

    const int grid = (E + EPB - 1) / EPB;
    edge_mlp_kernel<<<grid, TPB>>>(src, dst, ea, u, batch,
                                   W1, b1, W2, b2, (float*)d_out, E, B);
}

// round 8
// speedup vs baseline: 1.7863x; 1.4948x over previous
#include <cuda_runtime.h>

#define TPB   256
#define WARPS (TPB / 32)
#define EPW   32                 // edges per warp (ILP=1)
#define EPB   (WARPS * EPW)      // 256 edges per block

// Weights in constant memory: read via the constant port (LDC/LDCU),
// no L1tex wavefronts, no GPR cost for weight values.
__constant__ float cW1[40];      // [4][10] row-major
__constant__ float cb1[10];
__constant__ float cW2[190];     // [10][19] row-major
__constant__ float cb2[19];

// 1 if `batch` is int64 (odd int32 words are zero high-halves), else 0.
__device__ int g_batch_is64;

__global__ void detect_idx_kernel(const int* __restrict__ b32) {
    if (threadIdx.x == 0) {
        int z = 0;
#pragma unroll
        for (int i = 1; i < 64; i += 2) z |= b32[i];
        g_batch_is64 = (z == 0) ? 1 : 0;
    }
}

__global__ void __launch_bounds__(TPB, 4) edge_mlp_kernel(
    const float* __restrict__ src, const float* __restrict__ dst,
    const float* __restrict__ ea,  const float* __restrict__ u,
    const int* __restrict__ batch32,
    float* __restrict__ out, int E)
{
    __shared__ __align__(16) float wbuf[WARPS][EPW * 19];  // 2432 B per warp

    const int tid  = threadIdx.x;
    const int lane = tid & 31;
    const int w    = tid >> 5;
    const int is64 = g_batch_is64;                         // uniform

    const int we0 = blockIdx.x * EPB + w * EPW;            // warp's first edge
    const int e   = we0 + lane;
    const int ec  = (e < E) ? e : 0;

    // ---- coalesced streaming inputs + L1-resident u gather ----
    const float xs = __ldcs(src + ec);
    const float xd = __ldcs(dst + ec);
    const float xa = __ldcs(ea + ec);
    const int   bi = __ldcs(batch32 + ((size_t)ec << is64));
    const float xu = __ldg(u + bi);

    float o[19];
#pragma unroll
    for (int c = 0; c < 19; c++) o[c] = cb2[c];

    // ---- fused MLP, weights as constant-bank operands ----
#pragma unroll
    for (int j = 0; j < 10; j++) {
        float h = fmaf(xs, cW1[0 * 10 + j],
                  fmaf(xd, cW1[1 * 10 + j],
                  fmaf(xa, cW1[2 * 10 + j],
                  fmaf(xu, cW1[3 * 10 + j], cb1[j]))));
        h = fmaxf(h, 0.0f);
#pragma unroll
        for (int c = 0; c < 19; c++)
            o[c] = fmaf(h, cW2[j * 19 + c], o[c]);
    }

    // ---- stage to warp-private buffer (stride 19: conflict-free) ----
    if (e < E) {
#pragma unroll
        for (int c = 0; c < 19; c++) wbuf[w][lane * 19 + c] = o[c];
    }
    __syncwarp();

    // ---- coalesced streaming copy-out (warp base 16B-aligned: 32*76 B) ----
    int nv = E - we0;
    if (nv > EPW) nv = EPW;
    if (nv < 0)   nv = 0;
    const int nf  = nv * 19;
    const int nf4 = nf >> 2;
    float4* gout = reinterpret_cast<float4*>(out + (size_t)we0 * 19);
    const float4* sf = reinterpret_cast<const float4*>(&wbuf[w][0]);
#pragma unroll 5
    for (int i = lane; i < nf4; i += 32) __stcs(gout + i, sf[i]);
    if (lane < (nf & 3))
        out[(size_t)we0 * 19 + nf4 * 4 + lane] = wbuf[w][nf4 * 4 + lane];
}

extern "C" void kernel_launch(void* const* d_in, const int* in_sizes, int n_in,
                              void* d_out, int out_size)
{
    const float* src   = (const float*)d_in[0];
    const float* dst   = (const float*)d_in[1];
    const float* ea    = (const float*)d_in[2];
    const float* u     = (const float*)d_in[3];
    const int*   batch = (const int*)d_in[4];

    const int E = in_sizes[0];

    // Weights -> constant memory. Async D2D memcpys: graph-capture legal,
    // deterministic, run on every launch.
    cudaMemcpyToSymbolAsync(cW1, d_in[5],  40 * sizeof(float), 0,
                            cudaMemcpyDeviceToDevice, 0);
    cudaMemcpyToSymbolAsync(cb1, d_in[6],  10 * sizeof(float), 0,
                            cudaMemcpyDeviceToDevice, 0);
    cudaMemcpyToSymbolAsync(cW2, d_in[7], 190 * sizeof(float), 0,
                            cudaMemcpyDeviceToDevice, 0);
    cudaMemcpyToSymbolAsync(cb2, d_in[8],  19 * sizeof(float), 0,
                            cudaMemcpyDeviceToDevice, 0);

    detect_idx_kernel<<<1, 32>>>(batch);

    const int grid = (E + EPB - 1) / EPB;
    edge_mlp_kernel<<<grid, TPB>>>(src, dst, ea, u, batch, (float*)d_out, E);
}

// round 9
// speedup vs baseline: 1.9253x; 1.0778x over previous
#include <cuda_runtime.h>

#define TPB   256
#define WARPS (TPB / 32)
#define EPW   32                 // edges per warp (ILP=1)
#define EPB   (WARPS * EPW)      // 256 edges per block

// Weights in constant memory (constant-port reads, no L1tex wavefronts).
// cW2p/cb2p are channel-PADDED so (2k,2k+1) pairs are 8B-aligned for LDC.64;
// pad slots are never written and stay zero (static zero-init).
__constant__ __align__(8)  float cW1[40];        // [4][10] row-major
__constant__ __align__(8)  float cb1[10];
__constant__ __align__(16) float cW2p[10][20];   // [10][19] padded to 20, col19=0
__constant__ __align__(16) float cb2p[20];       // slot 19 = 0

// 1 if `batch` is int64 (odd int32 words are zero high-halves), else 0.
__device__ int g_batch_is64;

typedef unsigned long long u64;

__device__ __forceinline__ u64 pack2(float lo, float hi) {
    u64 r; asm("mov.b64 %0, {%1, %2};" : "=l"(r) : "f"(lo), "f"(hi)); return r;
}
__device__ __forceinline__ void unpack2(u64 v, float& lo, float& hi) {
    asm("mov.b64 {%0, %1}, %2;" : "=f"(lo), "=f"(hi) : "l"(v));
}
// Blackwell packed dual-fp32 FMA (2 FLOPs/instr; ptxas never auto-fuses this)
__device__ __forceinline__ u64 ffma2(u64 a, u64 b, u64 c) {
    u64 d; asm("fma.rn.f32x2 %0, %1, %2, %3;" : "=l"(d) : "l"(a), "l"(b), "l"(c));
    return d;
}
__device__ __forceinline__ u64 cpair(const float* p) {   // 8B-aligned const pair
    return *reinterpret_cast<const u64*>(p);
}

__global__ void detect_idx_kernel(const int* __restrict__ b32) {
    if (threadIdx.x == 0) {
        int z = 0;
#pragma unroll
        for (int i = 1; i < 64; i += 2) z |= b32[i];
        g_batch_is64 = (z == 0) ? 1 : 0;
    }
}

__global__ void __launch_bounds__(TPB, 4) edge_mlp_kernel(
    const float* __restrict__ src, const float* __restrict__ dst,
    const float* __restrict__ ea,  const float* __restrict__ u,
    const int* __restrict__ batch32,
    float* __restrict__ out, int E)
{
    __shared__ __align__(16) float wbuf[WARPS][EPW * 19];  // 2432 B per warp

    const int tid  = threadIdx.x;
    const int lane = tid & 31;
    const int w    = tid >> 5;
    const int is64 = g_batch_is64;                         // uniform

    const int we0 = blockIdx.x * EPB + w * EPW;            // warp's first edge
    const int e   = we0 + lane;
    const int ec  = (e < E) ? e : 0;

    // ---- coalesced streaming inputs + L1-resident u gather ----
    const float xs = __ldcs(src + ec);
    const float xd = __ldcs(dst + ec);
    const float xa = __ldcs(ea + ec);
    const int   bi = __ldcs(batch32 + ((size_t)ec << is64));
    const float xu = __ldg(u + bi);

    // broadcast-packed inputs for the packed hidden layer
    const u64 xsp = pack2(xs, xs);
    const u64 xdp = pack2(xd, xd);
    const u64 xap = pack2(xa, xa);
    const u64 xup = pack2(xu, xu);

    u64 op[10];                                            // packed output pairs

#pragma unroll
    for (int jp = 0; jp < 5; jp++) {
        // hidden pair (j = 2jp, 2jp+1): 4 FFMA2 + bias pair addend
        u64 hp = ffma2(xsp, cpair(&cW1[ 0 + 2*jp]),
                 ffma2(xdp, cpair(&cW1[10 + 2*jp]),
                 ffma2(xap, cpair(&cW1[20 + 2*jp]),
                 ffma2(xup, cpair(&cW1[30 + 2*jp]), cpair(&cb1[2*jp])))));
        float h0, h1; unpack2(hp, h0, h1);
        h0 = fmaxf(h0, 0.0f);
        h1 = fmaxf(h1, 0.0f);
        const u64 hb0 = pack2(h0, h0);
        const u64 hb1 = pack2(h1, h1);

        const int j0 = 2 * jp, j1 = 2 * jp + 1;
        if (jp == 0) {
#pragma unroll
            for (int k = 0; k < 10; k++)        // bias folded as addend
                op[k] = ffma2(hb0, cpair(&cW2p[j0][2*k]), cpair(&cb2p[2*k]));
        } else {
#pragma unroll
            for (int k = 0; k < 10; k++)
                op[k] = ffma2(hb0, cpair(&cW2p[j0][2*k]), op[k]);
        }
#pragma unroll
        for (int k = 0; k < 10; k++)
            op[k] = ffma2(hb1, cpair(&cW2p[j1][2*k]), op[k]);
    }

    // ---- stage to warp-private buffer (stride 19: conflict-free) ----
    if (e < E) {
#pragma unroll
        for (int k = 0; k < 9; k++) {
            float lo, hi; unpack2(op[k], lo, hi);
            wbuf[w][lane * 19 + 2*k    ] = lo;
            wbuf[w][lane * 19 + 2*k + 1] = hi;
        }
        float lo, hi; unpack2(op[9], lo, hi);
        wbuf[w][lane * 19 + 18] = lo;            // pad half (hi) discarded
    }
    __syncwarp();

    // ---- coalesced streaming copy-out (warp base 16B-aligned: 32*76 B) ----
    int nv = E - we0;
    if (nv > EPW) nv = EPW;
    if (nv < 0)   nv = 0;
    const int nf  = nv * 19;
    const int nf4 = nf >> 2;
    float4* gout = reinterpret_cast<float4*>(out + (size_t)we0 * 19);
    const float4* sf = reinterpret_cast<const float4*>(&wbuf[w][0]);
#pragma unroll 5
    for (int i = lane; i < nf4; i += 32) __stcs(gout + i, sf[i]);
    if (lane < (nf & 3))
        out[(size_t)we0 * 19 + nf4 * 4 + lane] = wbuf[w][nf4 * 4 + lane];
}

extern "C" void kernel_launch(void* const* d_in, const int* in_sizes, int n_in,
                              void* d_out, int out_size)
{
    const float* src   = (const float*)d_in[0];
    const float* dst   = (const float*)d_in[1];
    const float* ea    = (const float*)d_in[2];
    const float* u     = (const float*)d_in[3];
    const int*   batch = (const int*)d_in[4];
    const float* W2    = (const float*)d_in[7];

    const int E = in_sizes[0];

    // Weights -> constant memory (async D2D: graph-capture legal, deterministic).
    cudaMemcpyToSymbolAsync(cW1,  d_in[5], 40 * sizeof(float), 0,
                            cudaMemcpyDeviceToDevice, 0);
    cudaMemcpyToSymbolAsync(cb1,  d_in[6], 10 * sizeof(float), 0,
                            cudaMemcpyDeviceToDevice, 0);
    for (int j = 0; j < 10; j++)                 // row-wise into padded layout
        cudaMemcpyToSymbolAsync(cW2p, W2 + j * 19, 19 * sizeof(float),
                                j * 20 * sizeof(float),
                                cudaMemcpyDeviceToDevice, 0);
    cudaMemcpyToSymbolAsync(cb2p, d_in[8], 19 * sizeof(float), 0,
                            cudaMemcpyDeviceToDevice, 0);

    detect_idx_kernel<<<1, 32>>>(batch);

    const int grid = (E + EPB - 1) / EPB;
    edge_mlp_kernel<<<grid, TPB>>>(src, dst, ea, u, batch, (float*)d_out, E);
}